// round 1
// baseline (speedup 1.0000x reference)
#include <cuda_runtime.h>
#include <cuda_bf16.h>
#include <cstdint>

#define B_   2
#define N_   1024
#define DM   640
#define SH   5
#define DH   128
#define NH   14
#define KC   32

// -------- device scratch (no allocation allowed) --------
__device__ float g_qproj[B_ * N_ * SH * DH];   // (b,n,s,o)
__device__ float g_kproj[B_ * N_ * SH * DH];   // (b,n,s,o)
__device__ float g_vproj[B_ * N_ * NH * DH];   // (b,n,h,o)
__device__ float g_attn [B_ * N_ * NH * DH];   // (b,n,h,d)

__constant__ int c_dil [SH] = {1, 1, 2, 4, 8};
__constant__ int c_sub [NH] = {0,0,0,0,0, 1,1,1,1,1, 2,2, 3, 4};
__constant__ int c_dilh[NH] = {1,1,1,1,1, 1,1,1,1,1, 2,2, 4, 8};

// ---------------------------------------------------------------------------
// SGEMM with bias: C[m, o] = sum_d A[m,d] * W[o,d] + bias[o]
// A: (M, K) row-major,  W: (Nout, K) row-major, C: (M, Nout) row-major
// Requires M % 128 == 0, Nout % 128 == 0, K % 8 == 0 (true for all uses).
// Tile: 128x128, BK=8, 256 threads, 8x8 per thread.
// ---------------------------------------------------------------------------
__global__ __launch_bounds__(256) void gemm_bias_kernel(
    const float* __restrict__ A, const float* __restrict__ W,
    const float* __restrict__ bias, float* __restrict__ C,
    int M, int Nout, int K)
{
    __shared__ float As[8][128];
    __shared__ float Ws[8][128];

    const int bm  = blockIdx.y * 128;
    const int bn  = blockIdx.x * 128;
    const int tid = threadIdx.x;
    const int tx  = tid & 15;         // 0..15 -> 8 output cols each
    const int ty  = tid >> 4;         // 0..15 -> 8 output rows each

    const int lr = tid >> 1;          // 0..127 row to load
    const int lc = (tid & 1) * 4;     // 0 or 4

    float acc[8][8];
#pragma unroll
    for (int i = 0; i < 8; i++)
#pragma unroll
        for (int j = 0; j < 8; j++) acc[i][j] = 0.0f;

    const float* Arow = A + (size_t)(bm + lr) * K + lc;
    const float* Wrow = W + (size_t)(bn + lr) * K + lc;

    for (int k0 = 0; k0 < K; k0 += 8) {
        float4 a = *reinterpret_cast<const float4*>(Arow + k0);
        float4 w = *reinterpret_cast<const float4*>(Wrow + k0);
        __syncthreads();
        As[lc + 0][lr] = a.x; As[lc + 1][lr] = a.y;
        As[lc + 2][lr] = a.z; As[lc + 3][lr] = a.w;
        Ws[lc + 0][lr] = w.x; Ws[lc + 1][lr] = w.y;
        Ws[lc + 2][lr] = w.z; Ws[lc + 3][lr] = w.w;
        __syncthreads();

#pragma unroll
        for (int kk = 0; kk < 8; kk++) {
            float af[8], wf[8];
#pragma unroll
            for (int i = 0; i < 8; i++) af[i] = As[kk][ty * 8 + i];
#pragma unroll
            for (int j = 0; j < 8; j++) wf[j] = Ws[kk][tx * 8 + j];
#pragma unroll
            for (int i = 0; i < 8; i++)
#pragma unroll
                for (int j = 0; j < 8; j++) acc[i][j] += af[i] * wf[j];
        }
    }

#pragma unroll
    for (int i = 0; i < 8; i++) {
        const int row = bm + ty * 8 + i;
        float* crow = C + (size_t)row * Nout + bn + tx * 8;
#pragma unroll
        for (int j = 0; j < 8; j++) {
            crow[j] = acc[i][j] + bias[bn + tx * 8 + j];
        }
    }
}

// ---------------------------------------------------------------------------
// Fused banded attention: one CTA per (b, n).
//   Phase A: subhead scores  ssc[s][k] = q[b,n,s,:] . kwin(s,k)
//   Phase B: head scores     shs[h][j] = sum_k ssc[sub(h)][k]*Sk[h,j,k] + Sb
//   softmax over j, then
//   Phase C: attn[b,n,h,d] = sum_j w[h][j] * vwin(h,j,d)
// ---------------------------------------------------------------------------
__global__ __launch_bounds__(256) void attn_kernel(
    const float* __restrict__ Kb,   // (SH, DH)
    const float* __restrict__ Vb,   // (NH, DH)
    const float* __restrict__ Sk,   // (NH, KC, KC)
    const float* __restrict__ Sb)   // (NH, KC)
{
    const int n   = blockIdx.x;
    const int b   = blockIdx.y;
    const int tid = threadIdx.x;

    __shared__ float sq [SH * DH];   // q row            (640)
    __shared__ float ssc[SH * KC];   // subhead scores   (160)
    __shared__ float shs[NH * KC];   // head scores -> w (448)

    const float* qrow = g_qproj + (size_t)(b * N_ + n) * (SH * DH);
    for (int i = tid; i < SH * DH; i += 256) sq[i] = qrow[i];
    __syncthreads();

    // ---- Phase A: subhead banded scores ----
    if (tid < SH * KC) {
        const int s   = tid / KC;
        const int k   = tid % KC;
        const int dil = c_dil[s];
        const int pl  = ((KC - 1) * dil) >> 1;
        const int idx = n + k * dil - pl;
        const float* krow = (idx >= 0 && idx < N_)
            ? (g_kproj + (size_t)(b * N_ + idx) * (SH * DH) + s * DH)
            : (Kb + s * DH);
        const float4* k4 = reinterpret_cast<const float4*>(krow);
        const float4* q4 = reinterpret_cast<const float4*>(sq + s * DH);
        float acc = 0.0f;
#pragma unroll 8
        for (int d = 0; d < DH / 4; d++) {
            float4 kv = k4[d];
            float4 qv = q4[d];
            acc += qv.x * kv.x + qv.y * kv.y + qv.z * kv.z + qv.w * kv.w;
        }
        ssc[tid] = acc;
    }
    __syncthreads();

    // ---- Phase B: Pos_Sampling linear over k ----
    for (int t = tid; t < NH * KC; t += 256) {
        const int h = t / KC;
        const int j = t % KC;
        const int s = c_sub[h];
        const float* skrow = Sk + ((size_t)h * KC + j) * KC;
        const float* scrow = ssc + s * KC;
        float acc = Sb[h * KC + j];
#pragma unroll
        for (int k = 0; k < KC; k++) acc += scrow[k] * skrow[k];
        shs[t] = acc;
    }
    __syncthreads();

    // ---- softmax over j, per head ----
    if (tid < NH) {
        float* row = shs + tid * KC;
        float m = row[0];
#pragma unroll
        for (int j = 1; j < KC; j++) m = fmaxf(m, row[j]);
        float sum = 0.0f;
#pragma unroll
        for (int j = 0; j < KC; j++) { float e = expf(row[j] - m); row[j] = e; sum += e; }
        const float inv = 1.0f / sum;
#pragma unroll
        for (int j = 0; j < KC; j++) row[j] *= inv;
    }
    __syncthreads();

    // ---- Phase C: weighted gather of vwin; 2 heads per pass ----
    const int hh = tid / DH;     // 0 or 1
    const int d  = tid % DH;
    for (int hp = 0; hp < NH; hp += 2) {
        const int h   = hp + hh;
        const int dil = c_dilh[h];
        const int pl  = ((KC - 1) * dil) >> 1;
        const float* wrow = shs + h * KC;
        const float  vb   = Vb[h * DH + d];
        float acc = 0.0f;
#pragma unroll
        for (int j = 0; j < KC; j++) {
            const int idx = n + j * dil - pl;
            const float v = (idx >= 0 && idx < N_)
                ? g_vproj[(size_t)(b * N_ + idx) * (NH * DH) + h * DH + d]
                : vb;
            acc += wrow[j] * v;
        }
        g_attn[(size_t)(b * N_ + n) * (NH * DH) + h * DH + d] = acc;
    }
}

extern "C" void kernel_launch(void* const* d_in, const int* in_sizes, int n_in,
                              void* d_out, int out_size)
{
    const float* query = (const float*)d_in[0];
    const float* key   = (const float*)d_in[1];
    const float* value = (const float*)d_in[2];
    const float* Qk    = (const float*)d_in[3];
    const float* Qb    = (const float*)d_in[4];
    const float* Kk    = (const float*)d_in[5];
    const float* Kb    = (const float*)d_in[6];
    const float* Vk    = (const float*)d_in[7];
    const float* Vb    = (const float*)d_in[8];
    const float* Sk    = (const float*)d_in[9];
    const float* Sb    = (const float*)d_in[10];
    const float* Ck    = (const float*)d_in[11];
    const float* Cb    = (const float*)d_in[12];
    float* out = (float*)d_out;

    float *qp = nullptr, *kp = nullptr, *vp = nullptr, *ap = nullptr;
    cudaGetSymbolAddress((void**)&qp, g_qproj);
    cudaGetSymbolAddress((void**)&kp, g_kproj);
    cudaGetSymbolAddress((void**)&vp, g_vproj);
    cudaGetSymbolAddress((void**)&ap, g_attn);

    const int M = B_ * N_;  // 2048

    // Q / K projections: (2048, 640) = (2048, 640) x (640, 640)^T
    {
        dim3 grid(DM / 128, M / 128);   // (5, 16)
        gemm_bias_kernel<<<grid, 256>>>(query, Qk, Qb, qp, M, SH * DH, DM);
        gemm_bias_kernel<<<grid, 256>>>(key,   Kk, Kb, kp, M, SH * DH, DM);
    }
    // V projection: (2048, 1792)
    {
        dim3 grid((NH * DH) / 128, M / 128);  // (14, 16)
        gemm_bias_kernel<<<grid, 256>>>(value, Vk, Vb, vp, M, NH * DH, DM);
    }
    // Fused banded attention
    {
        dim3 grid(N_, B_);
        attn_kernel<<<grid, 256>>>(Kb, Vb, Sk, Sb);
    }
    // Collapse: (2048, 640) = (2048, 1792) x (640, 1792)^T
    {
        dim3 grid(DM / 128, M / 128);   // (5, 16)
        gemm_bias_kernel<<<grid, 256>>>(ap, Ck, Cb, out, M, DM, NH * DH);
    }
}